// round 5
// baseline (speedup 1.0000x reference)
#include <cuda_runtime.h>
#include <math.h>

#define NT     256
#define CPAD   260           // 260 % 32 == 4 -> conflict-free LDS.128 phases
#define B_     32
#define H_     1024
#define E_     512
#define V_     128
#define KA_    128
#define S_     256
#define VOCAB_ 8000
#define TSTEPS 128

// ---------------- persistent device state ----------------
__device__ float g_h1[2][B_ * H_];
__device__ float g_h2[2][B_ * H_];
__device__ float g_c1[B_ * H_];
__device__ float g_c2[B_ * H_];
__device__ float g_ctx[B_ * V_];

__device__ __forceinline__ float sigm(float x) { return 1.0f / (1.0f + expf(-x)); }

// ---------------- chunked GEMV core ----------------------
// acc[r] += dot(W[rows[r]][k0 : k0+4*klq], s_act[lane][0:4*klq])
// lane = batch. Weight reads warp-uniform; activation reads conflict-free.
template <int R>
__device__ __forceinline__ void gemv_chunk(float* acc, const int* rows,
                                           const float* __restrict__ W, int ldw,
                                           int k0, int klq,
                                           const float* s_act)
{
    const int lane = threadIdx.x & 31;
    const float4* xs = (const float4*)(s_act + lane * CPAD);
    const float4* wr[R];
#pragma unroll
    for (int r = 0; r < R; r++)
        wr[r] = (const float4*)(W + (size_t)rows[r] * (size_t)ldw + k0);
#pragma unroll 8
    for (int kq = 0; kq < klq; kq++) {
        float4 x4 = xs[kq];
#pragma unroll
        for (int r = 0; r < R; r++) {
            float4 w4 = wr[r][kq];
            acc[r] = fmaf(w4.x, x4.x, acc[r]);
            acc[r] = fmaf(w4.y, x4.y, acc[r]);
            acc[r] = fmaf(w4.z, x4.z, acc[r]);
            acc[r] = fmaf(w4.w, x4.w, acc[r]);
        }
    }
}

// Stage kl (=256 or 128) floats per batch from a flat [B][ld] source.
__device__ __forceinline__ void stage_flat(const float* __restrict__ src, int ld,
                                           int k0, int kl, float* s_act)
{
    const int klq = kl >> 2;
    const int sh  = (kl == 256) ? 6 : 5;
    for (int i = threadIdx.x; i < B_ * klq; i += NT) {
        int b  = i >> sh;
        int kq = i & (klq - 1);
        *(float4*)(s_act + b * CPAD + (kq << 2)) =
            *(const float4*)(src + (size_t)b * ld + k0 + (kq << 2));
    }
}

// ---------------- init: h1[0]=h2[0]=enc_hidden, c/ctx = 0 ---------------
__global__ void init_kernel(const float* __restrict__ enc_h)
{
    int i = blockIdx.x * blockDim.x + threadIdx.x;
    int n = gridDim.x * blockDim.x;
    for (int k = i; k < B_ * H_; k += n) {
        float v = enc_h[k];
        g_h1[0][k] = v;
        g_h2[0][k] = v;
        g_c1[k] = 0.f;
        g_c2[k] = 0.f;
    }
    for (int k = i; k < B_ * V_; k += n) g_ctx[k] = 0.f;
}

// ---------------- LSTM1: x=[emb|ctx] (640), hidden=h1 (1024) ------------
__global__ void __launch_bounds__(NT, 1)
lstm1_kernel(const int* __restrict__ tokens, const float* __restrict__ emb,
             const float* __restrict__ W_ih, const float* __restrict__ W_hh,
             const float* __restrict__ bias, int t, int p)
{
    __shared__ float s_act[B_ * CPAD];
    __shared__ float s_out[32 * 33];
    __shared__ int   s_tok[B_];

    const int tid = threadIdx.x, w = tid >> 5, lane = tid & 31;
    const int u0 = blockIdx.x * 8;                 // 128 CTAs * 8 units = 1024
    const float* h1p = g_h1[p];
    float*       h1n = g_h1[1 - p];

    if (tid < B_) s_tok[tid] = tokens[tid * (TSTEPS + 1) + t];

    int rows[4];
#pragma unroll
    for (int r = 0; r < 4; r++) {
        int l = w + 8 * r;                         // local row 0..31
        rows[r] = (l & 3) * H_ + (u0 + (l >> 2));  // gate*H + j
    }
    float acc[4] = {0.f, 0.f, 0.f, 0.f};

    // x part: chunks [0,256) [256,512) from embedding rows, [512,640) from ctx
#pragma unroll
    for (int c = 0; c < 3; c++) {
        int k0 = c * 256;
        int kl = (c == 2) ? 128 : 256;
        int klq = kl >> 2, sh = (kl == 256) ? 6 : 5;
        __syncthreads();
        for (int i = tid; i < B_ * klq; i += NT) {
            int b = i >> sh, kq = i & (klq - 1);
            const float* src = (k0 < E_)
                ? (emb + (size_t)s_tok[b] * E_ + k0)
                : (g_ctx + b * V_ + (k0 - E_));
            *(float4*)(s_act + b * CPAD + (kq << 2)) =
                *(const float4*)(src + (kq << 2));
        }
        __syncthreads();
        gemv_chunk<4>(acc, rows, W_ih, E_ + V_, k0, klq, s_act);
    }
    // hidden part: 4 chunks of 256 from h1_prev
#pragma unroll
    for (int c = 0; c < 4; c++) {
        int k0 = c * 256;
        __syncthreads();
        stage_flat(h1p, H_, k0, 256, s_act);
        __syncthreads();
        gemv_chunk<4>(acc, rows, W_hh, H_, k0, 64, s_act);
    }

    __syncthreads();
#pragma unroll
    for (int r = 0; r < 4; r++) s_out[(w + 8 * r) * 33 + lane] = acc[r];
    __syncthreads();

    {   // cell update: one (unit, batch) per thread
        int ul = tid >> 5, b = tid & 31;
        int j = u0 + ul;
        float ig = s_out[(4 * ul + 0) * 33 + b] + bias[j];
        float fg = s_out[(4 * ul + 1) * 33 + b] + bias[H_ + j];
        float gg = s_out[(4 * ul + 2) * 33 + b] + bias[2 * H_ + j];
        float og = s_out[(4 * ul + 3) * 33 + b] + bias[3 * H_ + j];
        float cn = sigm(fg) * g_c1[b * H_ + j] + sigm(ig) * tanhf(gg);
        g_c1[b * H_ + j] = cn;
        h1n[b * H_ + j] = sigm(og) * tanhf(cn);
    }
}

// ---------------- LSTM2: x=h1_new (1024), hidden=h2_prev (1024) ---------
__global__ void __launch_bounds__(NT, 1)
lstm2_kernel(const float* __restrict__ W_ih, const float* __restrict__ W_hh,
             const float* __restrict__ bias, int p)
{
    __shared__ float s_act[B_ * CPAD];
    __shared__ float s_out[32 * 33];

    const int tid = threadIdx.x, w = tid >> 5, lane = tid & 31;
    const int u0 = blockIdx.x * 8;
    const float* h1n = g_h1[1 - p];
    const float* h2p = g_h2[p];
    float*       h2n = g_h2[1 - p];

    int rows[4];
#pragma unroll
    for (int r = 0; r < 4; r++) {
        int l = w + 8 * r;
        rows[r] = (l & 3) * H_ + (u0 + (l >> 2));
    }
    float acc[4] = {0.f, 0.f, 0.f, 0.f};

#pragma unroll
    for (int c = 0; c < 4; c++) {
        int k0 = c * 256;
        __syncthreads();
        stage_flat(h1n, H_, k0, 256, s_act);
        __syncthreads();
        gemv_chunk<4>(acc, rows, W_ih, H_, k0, 64, s_act);
    }
#pragma unroll
    for (int c = 0; c < 4; c++) {
        int k0 = c * 256;
        __syncthreads();
        stage_flat(h2p, H_, k0, 256, s_act);
        __syncthreads();
        gemv_chunk<4>(acc, rows, W_hh, H_, k0, 64, s_act);
    }

    __syncthreads();
#pragma unroll
    for (int r = 0; r < 4; r++) s_out[(w + 8 * r) * 33 + lane] = acc[r];
    __syncthreads();

    {
        int ul = tid >> 5, b = tid & 31;
        int j = u0 + ul;
        float ig = s_out[(4 * ul + 0) * 33 + b] + bias[j];
        float fg = s_out[(4 * ul + 1) * 33 + b] + bias[H_ + j];
        float gg = s_out[(4 * ul + 2) * 33 + b] + bias[2 * H_ + j];
        float og = s_out[(4 * ul + 3) * 33 + b] + bias[3 * H_ + j];
        float cn = sigm(fg) * g_c2[b * H_ + j] + sigm(ig) * tanhf(gg);
        g_c2[b * H_ + j] = cn;
        h2n[b * H_ + j] = sigm(og) * tanhf(cn);
    }
}

// ---------------- attention: q, softmax, context (CTA = batch) ----------
__global__ void __launch_bounds__(NT, 1)
attn_kernel(const float* __restrict__ W_q, const float* __restrict__ b_q,
            const float* __restrict__ keys, const float* __restrict__ values,
            int p)
{
    __shared__ float sh2[H_];
    __shared__ float sq[KA_];
    __shared__ float se[S_];
    __shared__ float spart[8 * V_];
    __shared__ float sred[12];

    const int b = blockIdx.x;
    const int tid = threadIdx.x, w = tid >> 5, lane = tid & 31;
    const float* h2 = g_h2[1 - p] + b * H_;

    for (int i = tid; i < H_; i += NT) sh2[i] = h2[i];
    __syncthreads();

    // q[k] = h2 . W_q[k] + b_q[k]; warp w handles k = 16w..16w+15
#pragma unroll
    for (int kk = 0; kk < 16; kk++) {
        int k = w * 16 + kk;
        float a = 0.f;
        const float* wr = W_q + (size_t)k * H_;
#pragma unroll
        for (int m = 0; m < 32; m++) a = fmaf(wr[lane + 32 * m], sh2[lane + 32 * m], a);
#pragma unroll
        for (int off = 16; off > 0; off >>= 1) a += __shfl_down_sync(0xffffffffu, a, off);
        if (lane == 0) sq[k] = a + b_q[k];
    }
    __syncthreads();

    // energy[s] = keys[b][s] . q ; warp w handles s = 32w..32w+31
    const float* kb = keys + (size_t)b * S_ * KA_;
#pragma unroll
    for (int ss = 0; ss < 32; ss++) {
        int s = w * 32 + ss;
        const float* kr = kb + (size_t)s * KA_;
        float a = 0.f;
#pragma unroll
        for (int m = 0; m < 4; m++) a = fmaf(kr[lane + 32 * m], sq[lane + 32 * m], a);
#pragma unroll
        for (int off = 16; off > 0; off >>= 1) a += __shfl_down_sync(0xffffffffu, a, off);
        if (lane == 0) se[s] = a;
    }
    __syncthreads();

    // softmax over 256 (exact, max-subtracted); tid owns one element
    float e = se[tid];
    float m = e;
#pragma unroll
    for (int off = 16; off > 0; off >>= 1) m = fmaxf(m, __shfl_xor_sync(0xffffffffu, m, off));
    if (lane == 0) sred[w] = m;
    __syncthreads();
    if (tid == 0) {
        float mm = sred[0];
#pragma unroll
        for (int i = 1; i < 8; i++) mm = fmaxf(mm, sred[i]);
        sred[8] = mm;
    }
    __syncthreads();
    float pr = expf(e - sred[8]);
    se[tid] = pr;
    float s1 = pr;
#pragma unroll
    for (int off = 16; off > 0; off >>= 1) s1 += __shfl_xor_sync(0xffffffffu, s1, off);
    if (lane == 0) sred[w] = s1;
    __syncthreads();
    if (tid == 0) {
        float ss = 0.f;
#pragma unroll
        for (int i = 0; i < 8; i++) ss += sred[i];
        sred[9] = 1.0f / ss;
    }
    __syncthreads();
    float inv = sred[9];

    // context[v] = sum_s p_s * values[b][s][v]; warp w owns s-range, fixed-order combine
    const float* vb = values + (size_t)b * S_ * V_;
    float acc0 = 0.f, acc1 = 0.f, acc2 = 0.f, acc3 = 0.f;
#pragma unroll
    for (int ss = 0; ss < 32; ss++) {
        int s = w * 32 + ss;
        float ps = se[s];
        const float* vr = vb + (size_t)s * V_;
        acc0 = fmaf(ps, vr[lane], acc0);
        acc1 = fmaf(ps, vr[lane + 32], acc1);
        acc2 = fmaf(ps, vr[lane + 64], acc2);
        acc3 = fmaf(ps, vr[lane + 96], acc3);
    }
    spart[w * V_ + lane]      = acc0;
    spart[w * V_ + lane + 32] = acc1;
    spart[w * V_ + lane + 64] = acc2;
    spart[w * V_ + lane + 96] = acc3;
    __syncthreads();
    if (tid < V_) {
        float s = 0.f;
#pragma unroll
        for (int ww = 0; ww < 8; ww++) s += spart[ww * V_ + tid];
        g_ctx[b * V_ + tid] = s * inv;
    }
}

// ---------------- out: logits = [h2|ctx] @ W_out^T + b_out --------------
__global__ void __launch_bounds__(NT, 1)
out_kernel(const float* __restrict__ W_out, const float* __restrict__ b_out,
           float* __restrict__ out, int t, int p)
{
    __shared__ float s_act[B_ * CPAD];
    __shared__ float s_out[64 * 33];

    const int tid = threadIdx.x, w = tid >> 5, lane = tid & 31;
    const int n0 = blockIdx.x * 64;                // 125 CTAs * 64 = 8000
    const float* h2n = g_h2[1 - p];
    const int LD = H_ + V_;                        // 1152

    int rows[8];
#pragma unroll
    for (int r = 0; r < 8; r++) rows[r] = n0 + w + 8 * r;
    float acc[8] = {0.f, 0.f, 0.f, 0.f, 0.f, 0.f, 0.f, 0.f};

#pragma unroll
    for (int c = 0; c < 4; c++) {                  // h2 part: 4 x 256
        int k0 = c * 256;
        __syncthreads();
        stage_flat(h2n, H_, k0, 256, s_act);
        __syncthreads();
        gemv_chunk<8>(acc, rows, W_out, LD, k0, 64, s_act);
    }
    {                                              // ctx part: 128
        __syncthreads();
        stage_flat(g_ctx, V_, 0, 128, s_act);
        __syncthreads();
        gemv_chunk<8>(acc, rows, W_out, LD, H_, 32, s_act);
    }

    __syncthreads();
#pragma unroll
    for (int r = 0; r < 8; r++) s_out[(w + 8 * r) * 33 + lane] = acc[r];
    __syncthreads();

    for (int i = tid; i < 64 * B_; i += NT) {
        int b = i >> 6, l = i & 63;
        int n = n0 + l;
        out[((size_t)b * TSTEPS + t) * VOCAB_ + n] = s_out[l * 33 + b] + b_out[n];
    }
}

// ---------------- host ---------------------------------------------------
extern "C" void kernel_launch(void* const* d_in, const int* in_sizes, int n_in,
                              void* d_out, int out_size)
{
    const int*   tokens = (const int*)  d_in[0];
    // d_in[1] = inputs_lens (unused by reference output)
    const float* enc_h  = (const float*)d_in[2];
    const float* keys   = (const float*)d_in[3];
    const float* values = (const float*)d_in[4];
    const float* emb    = (const float*)d_in[5];
    const float* W_ih1  = (const float*)d_in[6];
    const float* W_hh1  = (const float*)d_in[7];
    const float* b1     = (const float*)d_in[8];
    const float* W_ih2  = (const float*)d_in[9];
    const float* W_hh2  = (const float*)d_in[10];
    const float* b2     = (const float*)d_in[11];
    const float* W_q    = (const float*)d_in[12];
    const float* b_q    = (const float*)d_in[13];
    const float* W_out  = (const float*)d_in[14];
    const float* b_out  = (const float*)d_in[15];
    float* out = (float*)d_out;

    init_kernel<<<64, NT>>>(enc_h);
    for (int t = 0; t < TSTEPS; t++) {
        int p = t & 1;
        lstm1_kernel<<<128, NT>>>(tokens, emb, W_ih1, W_hh1, b1, t, p);
        lstm2_kernel<<<128, NT>>>(W_ih2, W_hh2, b2, p);
        attn_kernel<<<B_, NT>>>(W_q, b_q, keys, values, p);
        out_kernel<<<125, NT>>>(W_out, b_out, out, t, p);
    }
}

// round 7
// speedup vs baseline: 1.0712x; 1.0712x over previous
#include <cuda_runtime.h>
#include <math.h>

#define NT     256
#define NTA    512
#define CPAD   260           // 260 % 32 == 4 -> conflict-free LDS.128 phases
#define B_     32
#define H_     1024
#define E_     512
#define V_     128
#define KA_    128
#define S_     256
#define VOCAB_ 8000
#define TSTEPS 128

// ---------------- persistent device state ----------------
__device__ float g_h1[2][B_ * H_];
__device__ float g_h2[2][B_ * H_];
__device__ float g_c1[B_ * H_];
__device__ float g_c2[B_ * H_];
__device__ float g_ctx[B_ * V_];

__device__ __forceinline__ float sigm(float x) { return 1.0f / (1.0f + expf(-x)); }

// ---------------- chunked GEMV core ----------------------
// acc[r] += dot(W[rows[r]][k0 : k0+4*klq], s_act[lane][0:4*klq])
// lane = batch. Weight reads warp-uniform; activation reads conflict-free.
template <int R>
__device__ __forceinline__ void gemv_chunk(float* acc, const int* rows,
                                           const float* __restrict__ W, int ldw,
                                           int k0, int klq,
                                           const float* s_act)
{
    const int lane = threadIdx.x & 31;
    const float4* xs = (const float4*)(s_act + lane * CPAD);
    const float4* wr[R];
#pragma unroll
    for (int r = 0; r < R; r++)
        wr[r] = (const float4*)(W + (size_t)rows[r] * (size_t)ldw + k0);
#pragma unroll 8
    for (int kq = 0; kq < klq; kq++) {
        float4 x4 = xs[kq];
#pragma unroll
        for (int r = 0; r < R; r++) {
            float4 w4 = wr[r][kq];
            acc[r] = fmaf(w4.x, x4.x, acc[r]);
            acc[r] = fmaf(w4.y, x4.y, acc[r]);
            acc[r] = fmaf(w4.z, x4.z, acc[r]);
            acc[r] = fmaf(w4.w, x4.w, acc[r]);
        }
    }
}

// Stage kl (=256 or 128) floats per batch from a flat [B][ld] source.
__device__ __forceinline__ void stage_flat(const float* __restrict__ src, int ld,
                                           int k0, int kl, float* s_act)
{
    const int klq = kl >> 2;
    const int sh  = (kl == 256) ? 6 : 5;
    for (int i = threadIdx.x; i < B_ * klq; i += NT) {
        int b  = i >> sh;
        int kq = i & (klq - 1);
        *(float4*)(s_act + b * CPAD + (kq << 2)) =
            *(const float4*)(src + (size_t)b * ld + k0 + (kq << 2));
    }
}

// ---------------- init: h1[0]=h2[0]=enc_hidden, c/ctx = 0 ---------------
__global__ void init_kernel(const float* __restrict__ enc_h)
{
    int i = blockIdx.x * blockDim.x + threadIdx.x;
    int n = gridDim.x * blockDim.x;
    for (int k = i; k < B_ * H_; k += n) {
        float v = enc_h[k];
        g_h1[0][k] = v;
        g_h2[0][k] = v;
        g_c1[k] = 0.f;
        g_c2[k] = 0.f;
    }
    for (int k = i; k < B_ * V_; k += n) g_ctx[k] = 0.f;
}

// ---------------- LSTM cell tail (4 units per CTA) ----------------------
__device__ __forceinline__ void lstm_tail(const float* s_out, const float* bias,
                                          float* c_state, float* h_dst, int u0)
{
    const int tid = threadIdx.x;
    if (tid < 128) {
        int ul = tid >> 5, b = tid & 31;
        int j = u0 + ul;
        float ig = s_out[(4 * ul + 0) * 33 + b] + bias[j];
        float fg = s_out[(4 * ul + 1) * 33 + b] + bias[H_ + j];
        float gg = s_out[(4 * ul + 2) * 33 + b] + bias[2 * H_ + j];
        float og = s_out[(4 * ul + 3) * 33 + b] + bias[3 * H_ + j];
        float cn = sigm(fg) * c_state[b * H_ + j] + sigm(ig) * tanhf(gg);
        c_state[b * H_ + j] = cn;
        h_dst[b * H_ + j] = sigm(og) * tanhf(cn);
    }
}

// ---------------- LSTM1: x=[emb|ctx] (640), hidden=h1 (1024) ------------
// 256 CTAs x 4 units (16 gate-rows); warp handles 2 rows.
__global__ void __launch_bounds__(NT, 2)
lstm1_kernel(const int* __restrict__ tokens, const float* __restrict__ emb,
             const float* __restrict__ W_ih, const float* __restrict__ W_hh,
             const float* __restrict__ bias, int t, int p)
{
    __shared__ float s_act[B_ * CPAD];
    __shared__ float s_out[16 * 33];
    __shared__ int   s_tok[B_];

    const int tid = threadIdx.x, w = tid >> 5, lane = tid & 31;
    const int u0 = blockIdx.x * 4;                 // 256 CTAs * 4 units = 1024
    const float* h1p = g_h1[p];
    float*       h1n = g_h1[1 - p];

    if (tid < B_) s_tok[tid] = tokens[tid * (TSTEPS + 1) + t];

    int rows[2];
#pragma unroll
    for (int r = 0; r < 2; r++) {
        int l = w + 8 * r;                         // local row 0..15
        rows[r] = (l & 3) * H_ + (u0 + (l >> 2));  // gate*H + j
    }
    float acc[2] = {0.f, 0.f};

    // x part: chunks [0,256) [256,512) from embedding rows, [512,640) from ctx
#pragma unroll
    for (int c = 0; c < 3; c++) {
        int k0 = c * 256;
        int kl = (c == 2) ? 128 : 256;
        int klq = kl >> 2, sh = (kl == 256) ? 6 : 5;
        __syncthreads();
        for (int i = tid; i < B_ * klq; i += NT) {
            int b = i >> sh, kq = i & (klq - 1);
            const float* src = (k0 < E_)
                ? (emb + (size_t)s_tok[b] * E_ + k0)
                : (g_ctx + b * V_ + (k0 - E_));
            *(float4*)(s_act + b * CPAD + (kq << 2)) =
                *(const float4*)(src + (kq << 2));
        }
        __syncthreads();
        gemv_chunk<2>(acc, rows, W_ih, E_ + V_, k0, klq, s_act);
    }
    // hidden part: 4 chunks of 256 from h1_prev
#pragma unroll
    for (int c = 0; c < 4; c++) {
        int k0 = c * 256;
        __syncthreads();
        stage_flat(h1p, H_, k0, 256, s_act);
        __syncthreads();
        gemv_chunk<2>(acc, rows, W_hh, H_, k0, 64, s_act);
    }

    __syncthreads();
#pragma unroll
    for (int r = 0; r < 2; r++) s_out[(w + 8 * r) * 33 + lane] = acc[r];
    __syncthreads();
    lstm_tail(s_out, bias, g_c1, h1n, u0);
}

// ---------------- LSTM2: x=h1_new (1024), hidden=h2_prev (1024) ---------
__global__ void __launch_bounds__(NT, 2)
lstm2_kernel(const float* __restrict__ W_ih, const float* __restrict__ W_hh,
             const float* __restrict__ bias, int p)
{
    __shared__ float s_act[B_ * CPAD];
    __shared__ float s_out[16 * 33];

    const int tid = threadIdx.x, w = tid >> 5, lane = tid & 31;
    const int u0 = blockIdx.x * 4;
    const float* h1n = g_h1[1 - p];
    const float* h2p = g_h2[p];
    float*       h2n = g_h2[1 - p];

    int rows[2];
#pragma unroll
    for (int r = 0; r < 2; r++) {
        int l = w + 8 * r;
        rows[r] = (l & 3) * H_ + (u0 + (l >> 2));
    }
    float acc[2] = {0.f, 0.f};

#pragma unroll
    for (int c = 0; c < 4; c++) {
        int k0 = c * 256;
        __syncthreads();
        stage_flat(h1n, H_, k0, 256, s_act);
        __syncthreads();
        gemv_chunk<2>(acc, rows, W_ih, H_, k0, 64, s_act);
    }
#pragma unroll
    for (int c = 0; c < 4; c++) {
        int k0 = c * 256;
        __syncthreads();
        stage_flat(h2p, H_, k0, 256, s_act);
        __syncthreads();
        gemv_chunk<2>(acc, rows, W_hh, H_, k0, 64, s_act);
    }

    __syncthreads();
#pragma unroll
    for (int r = 0; r < 2; r++) s_out[(w + 8 * r) * 33 + lane] = acc[r];
    __syncthreads();
    lstm_tail(s_out, bias, g_c2, h2n, u0);
}

// ---------------- attention: q, softmax, context (CTA = batch, 512 thr) --
__global__ void __launch_bounds__(NTA, 1)
attn_kernel(const float* __restrict__ W_q, const float* __restrict__ b_q,
            const float* __restrict__ keys, const float* __restrict__ values,
            int p)
{
    __shared__ float sh2[H_];
    __shared__ float sq[KA_];
    __shared__ float se[S_];
    __shared__ float spart[16 * V_];
    __shared__ float sred[20];

    const int b = blockIdx.x;
    const int tid = threadIdx.x, w = tid >> 5, lane = tid & 31;
    const float* h2 = g_h2[1 - p] + b * H_;

    for (int i = tid; i < H_; i += NTA) sh2[i] = h2[i];
    __syncthreads();

    // q[k] = h2 . W_q[k] + b_q[k]; warp w handles k = 8w..8w+7
#pragma unroll
    for (int kk = 0; kk < 8; kk++) {
        int k = w * 8 + kk;
        float a = 0.f;
        const float* wr = W_q + (size_t)k * H_;
#pragma unroll 8
        for (int m = 0; m < 32; m++) a = fmaf(wr[lane + 32 * m], sh2[lane + 32 * m], a);
#pragma unroll
        for (int off = 16; off > 0; off >>= 1) a += __shfl_down_sync(0xffffffffu, a, off);
        if (lane == 0) sq[k] = a + b_q[k];
    }
    __syncthreads();

    // energy[s] = keys[b][s] . q ; warp w handles s = 16w..16w+15
    const float* kb = keys + (size_t)b * S_ * KA_;
#pragma unroll
    for (int ss = 0; ss < 16; ss++) {
        int s = w * 16 + ss;
        const float* kr = kb + (size_t)s * KA_;
        float a = 0.f;
#pragma unroll
        for (int m = 0; m < 4; m++) a = fmaf(kr[lane + 32 * m], sq[lane + 32 * m], a);
#pragma unroll
        for (int off = 16; off > 0; off >>= 1) a += __shfl_down_sync(0xffffffffu, a, off);
        if (lane == 0) se[s] = a;
    }
    __syncthreads();

    // softmax over 256 (exact, max-subtracted); first 256 threads own one elem
    float e = 0.f;
    if (tid < S_) {
        e = se[tid];
        float m = e;
#pragma unroll
        for (int off = 16; off > 0; off >>= 1) m = fmaxf(m, __shfl_xor_sync(0xffffffffu, m, off));
        if (lane == 0) sred[w] = m;
    }
    __syncthreads();
    if (tid == 0) {
        float mm = sred[0];
#pragma unroll
        for (int i = 1; i < 8; i++) mm = fmaxf(mm, sred[i]);
        sred[16] = mm;
    }
    __syncthreads();
    if (tid < S_) {
        float pr = expf(e - sred[16]);
        se[tid] = pr;
        float s1 = pr;
#pragma unroll
        for (int off = 16; off > 0; off >>= 1) s1 += __shfl_xor_sync(0xffffffffu, s1, off);
        if (lane == 0) sred[w] = s1;
    }
    __syncthreads();
    if (tid == 0) {
        float ss = 0.f;
#pragma unroll
        for (int i = 0; i < 8; i++) ss += sred[i];
        sred[17] = 1.0f / ss;
    }
    __syncthreads();
    float inv = sred[17];

    // context[v] = sum_s p_s * values[b][s][v]; warp w owns 16 s, fixed-order combine
    const float* vb = values + (size_t)b * S_ * V_;
    float acc0 = 0.f, acc1 = 0.f, acc2 = 0.f, acc3 = 0.f;
#pragma unroll
    for (int ss = 0; ss < 16; ss++) {
        int s = w * 16 + ss;
        float ps = se[s];
        const float* vr = vb + (size_t)s * V_;
        acc0 = fmaf(ps, vr[lane], acc0);
        acc1 = fmaf(ps, vr[lane + 32], acc1);
        acc2 = fmaf(ps, vr[lane + 64], acc2);
        acc3 = fmaf(ps, vr[lane + 96], acc3);
    }
    spart[w * V_ + lane]      = acc0;
    spart[w * V_ + lane + 32] = acc1;
    spart[w * V_ + lane + 64] = acc2;
    spart[w * V_ + lane + 96] = acc3;
    __syncthreads();
    if (tid < V_) {
        float s = 0.f;
#pragma unroll
        for (int ww = 0; ww < 16; ww++) s += spart[ww * V_ + tid];
        g_ctx[b * V_ + tid] = s * inv;
    }
}

// ---------------- out: logits = [h2|ctx] @ W_out^T + b_out --------------
// 500 CTAs x 16 rows; warp handles 2 rows.
__global__ void __launch_bounds__(NT, 2)
out_kernel(const float* __restrict__ W_out, const float* __restrict__ b_out,
           float* __restrict__ out, int t, int p)
{
    __shared__ float s_act[B_ * CPAD];
    __shared__ float s_out[16 * 33];

    const int tid = threadIdx.x, w = tid >> 5, lane = tid & 31;
    const int n0 = blockIdx.x * 16;                // 500 CTAs * 16 = 8000
    const float* h2n = g_h2[1 - p];
    const int LD = H_ + V_;                        // 1152

    int rows[2];
#pragma unroll
    for (int r = 0; r < 2; r++) rows[r] = n0 + w + 8 * r;
    float acc[2] = {0.f, 0.f};

#pragma unroll
    for (int c = 0; c < 4; c++) {                  // h2 part: 4 x 256
        int k0 = c * 256;
        __syncthreads();
        stage_flat(h2n, H_, k0, 256, s_act);
        __syncthreads();
        gemv_chunk<2>(acc, rows, W_out, LD, k0, 64, s_act);
    }
    {                                              // ctx part: 128
        __syncthreads();
        stage_flat(g_ctx, V_, 0, 128, s_act);
        __syncthreads();
        gemv_chunk<2>(acc, rows, W_out, LD, H_, 32, s_act);
    }

    __syncthreads();
#pragma unroll
    for (int r = 0; r < 2; r++) s_out[(w + 8 * r) * 33 + lane] = acc[r];
    __syncthreads();

    for (int i = tid; i < 16 * B_; i += NT) {
        int b = i >> 4, l = i & 15;
        int n = n0 + l;
        out[((size_t)b * TSTEPS + t) * VOCAB_ + n] = s_out[l * 33 + b] + b_out[n];
    }
}

// ---------------- host ---------------------------------------------------
extern "C" void kernel_launch(void* const* d_in, const int* in_sizes, int n_in,
                              void* d_out, int out_size)
{
    const int*   tokens = (const int*)  d_in[0];
    // d_in[1] = inputs_lens (unused by reference output)
    const float* enc_h  = (const float*)d_in[2];
    const float* keys   = (const float*)d_in[3];
    const float* values = (const float*)d_in[4];
    const float* emb    = (const float*)d_in[5];
    const float* W_ih1  = (const float*)d_in[6];
    const float* W_hh1  = (const float*)d_in[7];
    const float* b1     = (const float*)d_in[8];
    const float* W_ih2  = (const float*)d_in[9];
    const float* W_hh2  = (const float*)d_in[10];
    const float* b2     = (const float*)d_in[11];
    const float* W_q    = (const float*)d_in[12];
    const float* b_q    = (const float*)d_in[13];
    const float* W_out  = (const float*)d_in[14];
    const float* b_out  = (const float*)d_in[15];
    float* out = (float*)d_out;

    init_kernel<<<64, NT>>>(enc_h);
    for (int t = 0; t < TSTEPS; t++) {
        int p = t & 1;
        lstm1_kernel<<<256, NT>>>(tokens, emb, W_ih1, W_hh1, b1, t, p);
        lstm2_kernel<<<256, NT>>>(W_ih2, W_hh2, b2, p);
        attn_kernel<<<B_, NTA>>>(W_q, b_q, keys, values, p);
        out_kernel<<<500, NT>>>(W_out, b_out, out, t, p);
    }
}

// round 8
// speedup vs baseline: 1.6114x; 1.5042x over previous
#include <cuda_runtime.h>
#include <math.h>

#define B_     32
#define H_     1024
#define E_     512
#define V_     128
#define KA_    128
#define S_     256
#define VOCAB_ 8000
#define TSTEPS 128
#define NT     256
#define NTA    512

// ---------------- persistent device state ----------------
__device__ float g_h1[2][B_ * H_];
__device__ float g_h2[2][B_ * H_];
__device__ float g_c1[B_ * H_];
__device__ float g_c2[B_ * H_];
__device__ float g_ctx[B_ * V_];

__device__ __forceinline__ float sigm(float x) { return 1.0f / (1.0f + expf(-x)); }

// ---------------- cp.async helpers ----------------------
__device__ __forceinline__ void cp16(void* dst, const void* src) {
    unsigned d = (unsigned)__cvta_generic_to_shared(dst);
    asm volatile("cp.async.cg.shared.global [%0], [%1], 16;" :: "r"(d), "l"(src));
}
__device__ __forceinline__ void cp_commit() { asm volatile("cp.async.commit_group;"); }
__device__ __forceinline__ void cp_wait1()  { asm volatile("cp.async.wait_group 1;" ::: "memory"); }
__device__ __forceinline__ void cp_wait0()  { asm volatile("cp.async.wait_group 0;" ::: "memory"); }

// ---------------- pipelined 16-row GEMV core -------------
// CTA owns 16 weight rows; chunk = 128 K-columns. Double-buffered cp.async for
// both the weight tile (16x128) and the activation tile (32x128, XOR-swizzled).
// lane = batch; warp w accumulates rows w and w+8.
// Cfg provides: wrow(l, c) -> gmem ptr to 128-float weight slice of local row l
//               asrc(b, c) -> gmem ptr to 128-float activation slice of batch b
template <class Cfg>
__device__ __forceinline__ void run_pipe(const Cfg& cfg, int nch,
                                         float4 (*sa)[1024], float4 (*sw)[512],
                                         float& acc0, float& acc1)
{
    const int tid = threadIdx.x, w = tid >> 5, lane = tid & 31;

    auto issue = [&](int c) {
        int buf = c & 1;
#pragma unroll
        for (int j = 0; j < 4; j++) {               // act: 1024 float4
            int i = tid + j * NT;
            int b = i >> 5, q = i & 31;
            cp16(&sa[buf][b * 32 + (q ^ b)], cfg.asrc(b, c) + q * 4);
        }
#pragma unroll
        for (int j = 0; j < 2; j++) {               // weights: 512 float4
            int i = tid + j * NT;
            int l = i >> 5, q = i & 31;
            cp16(&sw[buf][l * 32 + q], cfg.wrow(l, c) + q * 4);
        }
        cp_commit();
    };

    issue(0); issue(1);
    for (int c = 0; c < nch; c++) {
        if (c + 1 < nch) cp_wait1(); else cp_wait0();
        __syncthreads();
        const int buf = c & 1;
        const float4* xs = &sa[buf][lane * 32];
        const float4* w0 = &sw[buf][w * 32];
        const float4* w1 = &sw[buf][(w + 8) * 32];
#pragma unroll 8
        for (int kq = 0; kq < 32; kq++) {
            float4 x4 = xs[kq ^ lane];
            float4 a4 = w0[kq];
            acc0 = fmaf(a4.x, x4.x, acc0); acc0 = fmaf(a4.y, x4.y, acc0);
            acc0 = fmaf(a4.z, x4.z, acc0); acc0 = fmaf(a4.w, x4.w, acc0);
            float4 b4 = w1[kq];
            acc1 = fmaf(b4.x, x4.x, acc1); acc1 = fmaf(b4.y, x4.y, acc1);
            acc1 = fmaf(b4.z, x4.z, acc1); acc1 = fmaf(b4.w, x4.w, acc1);
        }
        __syncthreads();
        if (c + 2 < nch) issue(c + 2);
    }
}

// ---------------- per-kernel configs ---------------------
struct CfgL1 {      // lstm1: x=[emb|ctx] (5 chunks) then h1 (8 chunks); nch=13
    const int* tokens; const float* emb;
    const float* Wih; const float* Whh; const float* h1p; int t; int u0;
    __device__ __forceinline__ const float* wrow(int l, int c) const {
        int grow = (l & 3) * H_ + u0 + (l >> 2);
        return (c < 5) ? Wih + (size_t)grow * (E_ + V_) + c * 128
                       : Whh + (size_t)grow * H_ + (c - 5) * 128;
    }
    __device__ __forceinline__ const float* asrc(int b, int c) const {
        if (c < 4) {
            int tk = __ldg(&tokens[b * (TSTEPS + 1) + t]);
            return emb + (size_t)tk * E_ + c * 128;
        }
        if (c == 4) return g_ctx + b * V_;
        return h1p + b * H_ + (c - 5) * 128;
    }
};

struct CfgL2 {      // lstm2: h1 (8 chunks) then h2 (8 chunks); nch=16
    const float* Wih; const float* Whh; const float* h1n; const float* h2p; int u0;
    __device__ __forceinline__ const float* wrow(int l, int c) const {
        int grow = (l & 3) * H_ + u0 + (l >> 2);
        return (c < 8) ? Wih + (size_t)grow * H_ + c * 128
                       : Whh + (size_t)grow * H_ + (c - 8) * 128;
    }
    __device__ __forceinline__ const float* asrc(int b, int c) const {
        return (c < 8) ? h1n + b * H_ + c * 128
                       : h2p + b * H_ + (c - 8) * 128;
    }
};

struct CfgOut {     // out: [h2|ctx] (8 + 1 chunks); nch=9
    const float* W; const float* h2n; int n0;
    __device__ __forceinline__ const float* wrow(int l, int c) const {
        return W + (size_t)(n0 + l) * (H_ + V_) + c * 128;
    }
    __device__ __forceinline__ const float* asrc(int b, int c) const {
        return (c < 8) ? h2n + b * H_ + c * 128 : g_ctx + b * V_;
    }
};

// ---------------- lstm cell tail (4 units per CTA) -------
__device__ __forceinline__ void lstm_tail(const float* s_out, const float* bias,
                                          float* c_state, float* h_dst, int u0)
{
    const int tid = threadIdx.x;
    if (tid < 128) {
        int ul = tid >> 5, b = tid & 31;
        int j = u0 + ul;
        float ig = s_out[(4 * ul + 0) * 33 + b] + bias[j];
        float fg = s_out[(4 * ul + 1) * 33 + b] + bias[H_ + j];
        float gg = s_out[(4 * ul + 2) * 33 + b] + bias[2 * H_ + j];
        float og = s_out[(4 * ul + 3) * 33 + b] + bias[3 * H_ + j];
        float cn = sigm(fg) * c_state[b * H_ + j] + sigm(ig) * tanhf(gg);
        c_state[b * H_ + j] = cn;
        h_dst[b * H_ + j] = sigm(og) * tanhf(cn);
    }
}

// ---------------- init -----------------------------------
__global__ void init_kernel(const float* __restrict__ enc_h)
{
    int i = blockIdx.x * blockDim.x + threadIdx.x;
    int n = gridDim.x * blockDim.x;
    for (int k = i; k < B_ * H_; k += n) {
        float v = enc_h[k];
        g_h1[0][k] = v;
        g_h2[0][k] = v;
        g_c1[k] = 0.f;
        g_c2[k] = 0.f;
    }
    for (int k = i; k < B_ * V_; k += n) g_ctx[k] = 0.f;
}

// ---------------- lstm2 (256 CTAs x 4 units) -------------
__global__ void __launch_bounds__(NT, 2)
lstm2_kernel(const float* __restrict__ W_ih, const float* __restrict__ W_hh,
             const float* __restrict__ bias, int p)
{
    __shared__ float4 sa[2][1024];
    __shared__ float4 sw[2][512];
    const int tid = threadIdx.x, w = tid >> 5, lane = tid & 31;
    const int u0 = blockIdx.x * 4;

    CfgL2 cfg{W_ih, W_hh, g_h1[1 - p], g_h2[p], u0};
    float acc0 = 0.f, acc1 = 0.f;
    run_pipe(cfg, 16, sa, sw, acc0, acc1);

    float* s_out = (float*)sw;          // weight buffers free after last chunk
    s_out[w * 33 + lane] = acc0;
    s_out[(w + 8) * 33 + lane] = acc1;
    __syncthreads();
    lstm_tail(s_out, bias, g_c2, g_h2[1 - p], u0);
}

// ---------------- fused: out(t_out) || lstm1(t_l1) -------
// CTAs [0,500): out rows n0=cta*16; CTAs [500,756): lstm1 units u0=(cta-500)*4
__global__ void __launch_bounds__(NT, 2)
fused_kernel(const int* __restrict__ tokens, const float* __restrict__ emb,
             const float* __restrict__ W_ih1, const float* __restrict__ W_hh1,
             const float* __restrict__ b1,
             const float* __restrict__ W_out, const float* __restrict__ b_out,
             float* __restrict__ out, int t_out, int t_l1)
{
    __shared__ float4 sa[2][1024];
    __shared__ float4 sw[2][512];
    const int tid = threadIdx.x, w = tid >> 5, lane = tid & 31;

    if (blockIdx.x < 500) {
        if (t_out < 0) return;
        const int p = t_out & 1;
        const int n0 = blockIdx.x * 16;
        CfgOut cfg{W_out, g_h2[1 - p], n0};
        float acc0 = 0.f, acc1 = 0.f;
        run_pipe(cfg, 9, sa, sw, acc0, acc1);

        float* s_out = (float*)sw;
        s_out[w * 33 + lane] = acc0;
        s_out[(w + 8) * 33 + lane] = acc1;
        __syncthreads();
        for (int i = tid; i < 16 * B_; i += NT) {
            int b = i >> 4, l = i & 15;
            int n = n0 + l;
            out[((size_t)b * TSTEPS + t_out) * VOCAB_ + n] = s_out[l * 33 + b] + b_out[n];
        }
    } else {
        if (t_l1 >= TSTEPS) return;
        const int p1 = t_l1 & 1;
        const int u0 = (blockIdx.x - 500) * 4;
        CfgL1 cfg{tokens, emb, W_ih1, W_hh1, g_h1[p1], t_l1, u0};
        float acc0 = 0.f, acc1 = 0.f;
        run_pipe(cfg, 13, sa, sw, acc0, acc1);

        float* s_out = (float*)sw;
        s_out[w * 33 + lane] = acc0;
        s_out[(w + 8) * 33 + lane] = acc1;
        __syncthreads();
        lstm_tail(s_out, b1, g_c1, g_h1[1 - p1], u0);
    }
}

// ---------------- attention (CTA = batch, 512 threads) ----
__global__ void __launch_bounds__(NTA, 1)
attn_kernel(const float* __restrict__ W_q, const float* __restrict__ b_q,
            const float* __restrict__ keys, const float* __restrict__ values,
            int p)
{
    __shared__ float sh2[H_];
    __shared__ float sq[KA_];
    __shared__ float se[S_];
    __shared__ float spart[16 * V_];
    __shared__ float sred[20];

    const int b = blockIdx.x;
    const int tid = threadIdx.x, w = tid >> 5, lane = tid & 31;
    const float* h2 = g_h2[1 - p] + b * H_;

    for (int i = tid; i < H_; i += NTA) sh2[i] = h2[i];
    __syncthreads();

#pragma unroll
    for (int kk = 0; kk < 8; kk++) {
        int k = w * 8 + kk;
        float a = 0.f;
        const float* wr = W_q + (size_t)k * H_;
#pragma unroll 8
        for (int m = 0; m < 32; m++) a = fmaf(wr[lane + 32 * m], sh2[lane + 32 * m], a);
#pragma unroll
        for (int off = 16; off > 0; off >>= 1) a += __shfl_down_sync(0xffffffffu, a, off);
        if (lane == 0) sq[k] = a + b_q[k];
    }
    __syncthreads();

    const float* kb = keys + (size_t)b * S_ * KA_;
#pragma unroll
    for (int ss = 0; ss < 16; ss++) {
        int s = w * 16 + ss;
        const float* kr = kb + (size_t)s * KA_;
        float a = 0.f;
#pragma unroll
        for (int m = 0; m < 4; m++) a = fmaf(kr[lane + 32 * m], sq[lane + 32 * m], a);
#pragma unroll
        for (int off = 16; off > 0; off >>= 1) a += __shfl_down_sync(0xffffffffu, a, off);
        if (lane == 0) se[s] = a;
    }
    __syncthreads();

    float e = 0.f;
    if (tid < S_) {
        e = se[tid];
        float m = e;
#pragma unroll
        for (int off = 16; off > 0; off >>= 1) m = fmaxf(m, __shfl_xor_sync(0xffffffffu, m, off));
        if (lane == 0) sred[w] = m;
    }
    __syncthreads();
    if (tid == 0) {
        float mm = sred[0];
#pragma unroll
        for (int i = 1; i < 8; i++) mm = fmaxf(mm, sred[i]);
        sred[16] = mm;
    }
    __syncthreads();
    if (tid < S_) {
        float pr = expf(e - sred[16]);
        se[tid] = pr;
        float s1 = pr;
#pragma unroll
        for (int off = 16; off > 0; off >>= 1) s1 += __shfl_xor_sync(0xffffffffu, s1, off);
        if (lane == 0) sred[w] = s1;
    }
    __syncthreads();
    if (tid == 0) {
        float ss = 0.f;
#pragma unroll
        for (int i = 0; i < 8; i++) ss += sred[i];
        sred[17] = 1.0f / ss;
    }
    __syncthreads();
    float inv = sred[17];

    const float* vb = values + (size_t)b * S_ * V_;
    float acc0 = 0.f, acc1 = 0.f, acc2 = 0.f, acc3 = 0.f;
#pragma unroll
    for (int ss = 0; ss < 16; ss++) {
        int s = w * 16 + ss;
        float ps = se[s];
        const float* vr = vb + (size_t)s * V_;
        acc0 = fmaf(ps, vr[lane], acc0);
        acc1 = fmaf(ps, vr[lane + 32], acc1);
        acc2 = fmaf(ps, vr[lane + 64], acc2);
        acc3 = fmaf(ps, vr[lane + 96], acc3);
    }
    spart[w * V_ + lane]      = acc0;
    spart[w * V_ + lane + 32] = acc1;
    spart[w * V_ + lane + 64] = acc2;
    spart[w * V_ + lane + 96] = acc3;
    __syncthreads();
    if (tid < V_) {
        float s = 0.f;
#pragma unroll
        for (int ww = 0; ww < 16; ww++) s += spart[ww * V_ + tid];
        g_ctx[b * V_ + tid] = s * inv;
    }
}

// ---------------- host -----------------------------------
extern "C" void kernel_launch(void* const* d_in, const int* in_sizes, int n_in,
                              void* d_out, int out_size)
{
    const int*   tokens = (const int*)  d_in[0];
    const float* enc_h  = (const float*)d_in[2];
    const float* keys   = (const float*)d_in[3];
    const float* values = (const float*)d_in[4];
    const float* emb    = (const float*)d_in[5];
    const float* W_ih1  = (const float*)d_in[6];
    const float* W_hh1  = (const float*)d_in[7];
    const float* b1     = (const float*)d_in[8];
    const float* W_ih2  = (const float*)d_in[9];
    const float* W_hh2  = (const float*)d_in[10];
    const float* b2     = (const float*)d_in[11];
    const float* W_q    = (const float*)d_in[12];
    const float* b_q    = (const float*)d_in[13];
    const float* W_out  = (const float*)d_in[14];
    const float* b_out  = (const float*)d_in[15];
    float* out = (float*)d_out;

    init_kernel<<<64, NT>>>(enc_h);
    // lstm1(0) only
    fused_kernel<<<756, NT>>>(tokens, emb, W_ih1, W_hh1, b1,
                              W_out, b_out, out, -1, 0);
    for (int t = 0; t < TSTEPS; t++) {
        int p = t & 1;
        lstm2_kernel<<<256, NT>>>(W_ih2, W_hh2, b2, p);
        attn_kernel<<<B_, NTA>>>(W_q, b_q, keys, values, p);
        fused_kernel<<<756, NT>>>(tokens, emb, W_ih1, W_hh1, b1,
                                  W_out, b_out, out, t, t + 1);
    }
}